// round 15
// baseline (speedup 1.0000x reference)
#include <cuda_runtime.h>
#include <cstdint>

#define N_TOK   65536
#define K_IN    64
#define E_DIM   512
#define V_SIZE  2048
#define NCHUNK  2
#define VCHUNK  (V_SIZE / NCHUNK)
#define PKB     4                    // pmat split-K factor
#define NBX_DIST (N_TOK / 128)       // 512 dist blocks in x
#define NBX_PMAT (V_SIZE / 64 * PKB / NCHUNK)   // 64 extra x-blocks (x2 chunks = 128)
#define NBX_PRE  (N_TOK / 64)        // 1024 pre blocks in x
#define NBX_E2   (V_SIZE / 2)        // 1024 extra x-blocks (2 codes each)

typedef unsigned long long ull;

// ---- scratch ----
__device__ float g_zp[(size_t)N_TOK * E_DIM];
__device__ float g_Cp[4][N_TOK];                 // per-j-block |zp|^2 partials
__device__ float g_e2[V_SIZE];
__device__ float g_Pp[PKB][(size_t)V_SIZE * 64]; // pmat k-partials
__device__ float g_pv[NCHUNK][N_TOK];
__device__ int   g_pi[NCHUNK][N_TOK];

// ---- packed fp32x2 helpers (exact IEEE fp32 per lane) ----
__device__ __forceinline__ ull fma2(ull a, ull b, ull c) {
    ull d; asm("fma.rn.f32x2 %0, %1, %2, %3;" : "=l"(d) : "l"(a), "l"(b), "l"(c)); return d;
}
__device__ __forceinline__ ull dup2(float x) {
    ull d; asm("mov.b64 %0, {%1, %1};" : "=l"(d) : "f"(x)); return d;
}
__device__ __forceinline__ ull pack2(float x, float y) {
    ull d; asm("mov.b64 %0, {%1, %2};" : "=l"(d) : "f"(x), "f"(y)); return d;
}
__device__ __forceinline__ float2 unpack2(ull v) {
    float2 r; asm("mov.b64 {%0, %1}, %2;" : "=f"(r.x), "=f"(r.y) : "l"(v)); return r;
}

// ============================================================
// e2 body: bitwise-exact replica of the validated e2_kernel,
// executed by a 128-thread half of a fused pre_gemm block.
// (identical k stride-128 fmaf chain, identical warp shfl tree,
//  identical ws[0..3] summation order)
// ============================================================
__device__ __forceinline__ void e2_body(const float* __restrict__ emb, int v)
{
    __shared__ float ws2[2][4];
    int ltid = threadIdx.x & 127;
    int half = threadIdx.x >> 7;

    const float* row = emb + (size_t)v * E_DIM;
    float s = 0.f;
    for (int k = ltid; k < E_DIM; k += 128) {
        float x = row[k];
        s = fmaf(x, x, s);
    }
    for (int off = 16; off > 0; off >>= 1)
        s += __shfl_down_sync(0xffffffffu, s, off);
    int lane = ltid & 31, warp = ltid >> 5;
    if (lane == 0) ws2[half][warp] = s;
    __syncthreads();
    if (ltid == 0)
        g_e2[v] = ws2[half][0] + ws2[half][1] + ws2[half][2] + ws2[half][3];
}

// ============================================================
// Kernel 1: tiled pre GEMM + fused C partials (validated R10)
// + e2 blocks appended in x (blockIdx.x >= NBX_PRE, y == 0)
// ============================================================
__global__ __launch_bounds__(256) void pre_gemm(
    const float* __restrict__ z, const float* __restrict__ W,
    const float* __restrict__ b, const float* __restrict__ emb)
{
    if (blockIdx.x >= NBX_PRE) {
        if (blockIdx.y != 0) return;
        int ex = blockIdx.x - NBX_PRE;
        e2_body(emb, ex * 2 + (threadIdx.x >> 7));
        return;
    }

    __shared__ float As[64][64];
    __shared__ float Ws[64][128];

    int m0 = blockIdx.x * 64;
    int jb = blockIdx.y;
    int j0 = jb * 128;
    int tid = threadIdx.x;
    int tx = tid & 15;
    int ty = tid >> 4;

    #pragma unroll
    for (int l = 0; l < 4; l++) {
        int idx = tid + 256 * l;
        int row = idx >> 4, q = idx & 15;
        float4 v = *(const float4*)(z + (size_t)(m0 + row) * K_IN + q * 4);
        *(float4*)&As[row][q * 4] = v;
    }
    #pragma unroll
    for (int l = 0; l < 8; l++) {
        int idx = tid + 256 * l;
        int row = idx >> 5, q = idx & 31;
        float4 v = *(const float4*)(W + (size_t)row * E_DIM + j0 + q * 4);
        *(float4*)&Ws[row][q * 4] = v;
    }
    __syncthreads();

    float4 bl0 = *(const float4*)&b[j0 + tx * 8];
    float4 bl1 = *(const float4*)&b[j0 + tx * 8 + 4];
    ull acc[4][4];
    #pragma unroll
    for (int i = 0; i < 4; i++) {
        acc[i][0] = pack2(bl0.x, bl0.y);
        acc[i][1] = pack2(bl0.z, bl0.w);
        acc[i][2] = pack2(bl1.x, bl1.y);
        acc[i][3] = pack2(bl1.z, bl1.w);
    }

    #pragma unroll 8
    for (int kk = 0; kk < K_IN; kk++) {
        float a0 = As[ty * 4 + 0][kk];
        float a1 = As[ty * 4 + 1][kk];
        float a2 = As[ty * 4 + 2][kk];
        float a3 = As[ty * 4 + 3][kk];
        float4 w0 = *(const float4*)&Ws[kk][tx * 8];
        float4 w1 = *(const float4*)&Ws[kk][tx * 8 + 4];
        ull b0 = pack2(w0.x, w0.y), b1 = pack2(w0.z, w0.w);
        ull b2 = pack2(w1.x, w1.y), b3 = pack2(w1.z, w1.w);
        ull ad0 = dup2(a0), ad1 = dup2(a1), ad2 = dup2(a2), ad3 = dup2(a3);
        acc[0][0] = fma2(ad0, b0, acc[0][0]); acc[0][1] = fma2(ad0, b1, acc[0][1]);
        acc[0][2] = fma2(ad0, b2, acc[0][2]); acc[0][3] = fma2(ad0, b3, acc[0][3]);
        acc[1][0] = fma2(ad1, b0, acc[1][0]); acc[1][1] = fma2(ad1, b1, acc[1][1]);
        acc[1][2] = fma2(ad1, b2, acc[1][2]); acc[1][3] = fma2(ad1, b3, acc[1][3]);
        acc[2][0] = fma2(ad2, b0, acc[2][0]); acc[2][1] = fma2(ad2, b1, acc[2][1]);
        acc[2][2] = fma2(ad2, b2, acc[2][2]); acc[2][3] = fma2(ad2, b3, acc[2][3]);
        acc[3][0] = fma2(ad3, b0, acc[3][0]); acc[3][1] = fma2(ad3, b1, acc[3][1]);
        acc[3][2] = fma2(ad3, b2, acc[3][2]); acc[3][3] = fma2(ad3, b3, acc[3][3]);
    }

    #pragma unroll
    for (int i = 0; i < 4; i++) {
        int n = m0 + ty * 4 + i;
        float2 p0 = unpack2(acc[i][0]), p1 = unpack2(acc[i][1]);
        float2 p2 = unpack2(acc[i][2]), p3 = unpack2(acc[i][3]);
        float4 r0; r0.x = p0.x; r0.y = p0.y; r0.z = p1.x; r0.w = p1.y;
        float4 r1; r1.x = p2.x; r1.y = p2.y; r1.z = p3.x; r1.w = p3.y;
        float* dst = g_zp + (size_t)n * E_DIM + j0 + tx * 8;
        *(float4*)dst = r0;
        *(float4*)(dst + 4) = r1;

        float s = r0.x * r0.x;
        s = fmaf(r0.y, r0.y, s);
        s = fmaf(r0.z, r0.z, s);
        s = fmaf(r0.w, r0.w, s);
        s = fmaf(r1.x, r1.x, s);
        s = fmaf(r1.y, r1.y, s);
        s = fmaf(r1.z, r1.z, s);
        s = fmaf(r1.w, r1.w, s);
        #pragma unroll
        for (int off = 8; off > 0; off >>= 1)
            s += __shfl_xor_sync(0xffffffffu, s, off);
        if (tx == 0) g_Cp[jb][n] = s;
    }
}

// ============================================================
// pmat body (split-K partials, PKB=4), executed by the extra
// blocks of the fused dist launch. Dynamic smem.
// ============================================================
__device__ __forceinline__ void pmat_body(
    const float* __restrict__ emb, const float* __restrict__ W, int ex)
{
    extern __shared__ float dsm[];
    float (*As2)[64 + 4] = (float(*)[64 + 4])dsm;              // [32][68]
    float (*Bs2)[64 + 4] = (float(*)[64 + 4])(dsm + 32 * 68);  // [32][68]

    int m0  = (ex & 31) * 64;
    int kb  = ex >> 5;                 // 0..3
    int tid = threadIdx.x;
    int tx  = tid & 15;
    int ty  = tid >> 4;

    float acc[4][4];
    #pragma unroll
    for (int i = 0; i < 4; i++)
        #pragma unroll
        for (int jj = 0; jj < 4; jj++) acc[i][jj] = 0.f;

    for (int k0 = kb * 128; k0 < kb * 128 + 128; k0 += 32) {
        #pragma unroll
        for (int i = 0; i < 8; i++) {
            int idx = tid + 256 * i;
            int m = idx >> 5, kk = idx & 31;
            As2[kk][m] = emb[(size_t)(m0 + m) * E_DIM + k0 + kk];
        }
        #pragma unroll
        for (int i = 0; i < 8; i++) {
            int idx = tid + 256 * i;
            int kk = idx >> 6, jj = idx & 63;
            Bs2[kk][jj] = W[(size_t)(k0 + kk) * 64 + jj];
        }
        __syncthreads();
        #pragma unroll
        for (int kk = 0; kk < 32; kk++) {
            float a[4], bb[4];
            *(float4*)a  = *(const float4*)&As2[kk][ty * 4];
            *(float4*)bb = *(const float4*)&Bs2[kk][tx * 4];
            #pragma unroll
            for (int i = 0; i < 4; i++)
                #pragma unroll
                for (int jj = 0; jj < 4; jj++)
                    acc[i][jj] = fmaf(a[i], bb[jj], acc[i][jj]);
        }
        __syncthreads();
    }

    #pragma unroll
    for (int i = 0; i < 4; i++) {
        int n = m0 + ty * 4 + i;
        float4 r;
        r.x = acc[i][0];
        r.y = acc[i][1];
        r.z = acc[i][2];
        r.w = acc[i][3];
        *(float4*)&g_Pp[kb][(size_t)n * 64 + tx * 4] = r;
    }
}

// ============================================================
// Kernel 2: fused distance GEMM + argmin (R11 code verbatim) +
// pmat blocks appended in x.  dist FMA chains identical ->
// bitwise tokens.
// ============================================================
#define DBM 128
#define DBV 256
#define DBK 16
#define NKT (E_DIM / DBK)          // 32
#define NVT (VCHUNK / DBV)         // 4
#define NT  (NKT * NVT)            // 128

__global__ __launch_bounds__(256, 1) void dist_kernel(
    const float* __restrict__ emb, const float* __restrict__ postW)
{
    if (blockIdx.x >= NBX_DIST) {
        int ex = (blockIdx.x - NBX_DIST) * NCHUNK + blockIdx.y;
        pmat_body(emb, postW, ex);
        return;
    }

    __shared__ float As[2][DBK][DBM];
    __shared__ float Bs[2][DBK][DBV];
    __shared__ float sE2[VCHUNK];

    int m0 = blockIdx.x * DBM;
    int chunk = blockIdx.y;
    int vc = chunk * VCHUNK;

    int tid = threadIdx.x;
    int tx  = tid & 15;
    int ty  = tid >> 4;
    int row0 = ty * 8;

    int mA  = tid >> 2;
    int kq4 = (tid & 3) * 4;
    int sw  = kq4 << 1;
    int mAx = mA ^ sw;

    const float* aBase = g_zp + (size_t)(m0 + mA) * E_DIM + kq4;
    const float* bBase = emb  + (size_t)(vc + mA) * E_DIM + kq4;

    float Ci[8];
    #pragma unroll
    for (int i = 0; i < 8; i++) {
        int n = m0 + row0 + i;
        Ci[i] = ((g_Cp[0][n] + g_Cp[1][n]) + g_Cp[2][n]) + g_Cp[3][n];
    }

    float bestv[8];
    int   besti[8];
    #pragma unroll
    for (int i = 0; i < 8; i++) { bestv[i] = 3.4e38f; besti[i] = 0; }

    ull acc[8][8];
    float4 pA0, pA1, pB0, pB1, pB2, pB3;

    #define LOAD_TILE(tt) do {                                              \
        int _k = ((tt) & (NKT - 1)) * DBK;                                  \
        int _v = ((tt) >> 5) * DBV;                                         \
        pA0 = *(const float4*)(aBase + _k);                                 \
        pA1 = *(const float4*)(aBase + (size_t)64 * E_DIM + _k);            \
        const float* _bb = bBase + (size_t)_v * E_DIM + _k;                 \
        pB0 = *(const float4*)(_bb);                                        \
        pB1 = *(const float4*)(_bb + (size_t)64  * E_DIM);                  \
        pB2 = *(const float4*)(_bb + (size_t)128 * E_DIM);                  \
        pB3 = *(const float4*)(_bb + (size_t)192 * E_DIM);                  \
    } while (0)

    #define STS_A_B01(bf) do {                                              \
        float* _a = &As[bf][kq4][0];                                        \
        _a[0*DBM + mAx]      = pA0.x; _a[1*DBM + mAx]      = pA0.y;         \
        _a[2*DBM + mAx]      = pA0.z; _a[3*DBM + mAx]      = pA0.w;         \
        _a[0*DBM + mAx + 64] = pA1.x; _a[1*DBM + mAx + 64] = pA1.y;         \
        _a[2*DBM + mAx + 64] = pA1.z; _a[3*DBM + mAx + 64] = pA1.w;         \
        float* _b = &Bs[bf][kq4][0];                                        \
        _b[0*DBV + mAx]       = pB0.x; _b[1*DBV + mAx]       = pB0.y;       \
        _b[2*DBV + mAx]       = pB0.z; _b[3*DBV + mAx]       = pB0.w;       \
        _b[0*DBV + mAx + 64]  = pB1.x; _b[1*DBV + mAx + 64]  = pB1.y;       \
        _b[2*DBV + mAx + 64]  = pB1.z; _b[3*DBV + mAx + 64]  = pB1.w;       \
    } while (0)

    #define STS_B23(bf) do {                                                \
        float* _b = &Bs[bf][kq4][0];                                        \
        _b[0*DBV + mAx + 128] = pB2.x; _b[1*DBV + mAx + 128] = pB2.y;       \
        _b[2*DBV + mAx + 128] = pB2.z; _b[3*DBV + mAx + 128] = pB2.w;       \
        _b[0*DBV + mAx + 192] = pB3.x; _b[1*DBV + mAx + 192] = pB3.y;       \
        _b[2*DBV + mAx + 192] = pB3.z; _b[3*DBV + mAx + 192] = pB3.w;       \
    } while (0)

    #define COMPUTE_KK(bf, kk) do {                                         \
        const int s = ((kk) & 12) << 1;                                     \
        float4 a01 = *(const float4*)&As[bf][kk][(row0 ^ s)];               \
        float4 a23 = *(const float4*)&As[bf][kk][(row0 ^ s) + 4];           \
        ull ad[8];                                                          \
        ad[0] = dup2(a01.x); ad[1] = dup2(a01.y);                           \
        ad[2] = dup2(a01.z); ad[3] = dup2(a01.w);                           \
        ad[4] = dup2(a23.x); ad[5] = dup2(a23.y);                           \
        ad[6] = dup2(a23.z); ad[7] = dup2(a23.w);                           \
        _Pragma("unroll")                                                   \
        for (int g = 0; g < 4; g++) {                                       \
            float4 b = *(const float4*)&Bs[bf][kk][(((g * 16 + tx) * 4) ^ s)]; \
            ull b0 = pack2(b.x, b.y);                                       \
            ull b1 = pack2(b.z, b.w);                                       \
            _Pragma("unroll")                                               \
            for (int i = 0; i < 8; i++) {                                   \
                acc[i][g * 2 + 0] = fma2(ad[i], b0, acc[i][g * 2 + 0]);     \
                acc[i][g * 2 + 1] = fma2(ad[i], b1, acc[i][g * 2 + 1]);     \
            }                                                               \
        }                                                                   \
    } while (0)

    LOAD_TILE(0);
    STS_A_B01(0);
    STS_B23(0);
    {
        float4 v = *(const float4*)&g_e2[vc + tid * 4];
        *(float4*)&sE2[tid * 4] = v;
    }
    LOAD_TILE(1);
    __syncthreads();

    for (int t = 0; t < NT; t++) {
        int buf = t & 1;
        bool more = (t + 1 < NT);

        if ((t & (NKT - 1)) == 0) {
            #pragma unroll
            for (int i = 0; i < 8; i++)
                #pragma unroll
                for (int j = 0; j < 8; j++) acc[i][j] = 0ull;
        }

        #pragma unroll
        for (int kk = 0; kk < 4; kk++) COMPUTE_KK(buf, kk);

        if (more) STS_A_B01(buf ^ 1);

        #pragma unroll
        for (int kk = 4; kk < 8; kk++) COMPUTE_KK(buf, kk);

        if (more) STS_B23(buf ^ 1);

        #pragma unroll
        for (int kk = 8; kk < 12; kk++) COMPUTE_KK(buf, kk);

        if (more) {
            int tt = (t + 2 < NT) ? t + 2 : NT - 1;
            LOAD_TILE(tt);
        }

        #pragma unroll
        for (int kk = 12; kk < DBK; kk++) COMPUTE_KK(buf, kk);

        __syncthreads();

        if ((t & (NKT - 1)) == NKT - 1) {
            int lv0 = (t >> 5) * DBV;
            #pragma unroll
            for (int g = 0; g < 4; g++) {
                int lvb = lv0 + (g * 16 + tx) * 4;
                float4 e4 = *(const float4*)&sE2[lvb];
                int vb = vc + lvb;
                #pragma unroll
                for (int i = 0; i < 8; i++) {
                    float2 p0 = unpack2(acc[i][g * 2 + 0]);
                    float2 p1 = unpack2(acc[i][g * 2 + 1]);
                    float d;
                    d = fmaf(-2.0f, p0.x, Ci[i] + e4.x);
                    if (d < bestv[i]) { bestv[i] = d; besti[i] = vb + 0; }
                    d = fmaf(-2.0f, p0.y, Ci[i] + e4.y);
                    if (d < bestv[i]) { bestv[i] = d; besti[i] = vb + 1; }
                    d = fmaf(-2.0f, p1.x, Ci[i] + e4.z);
                    if (d < bestv[i]) { bestv[i] = d; besti[i] = vb + 2; }
                    d = fmaf(-2.0f, p1.y, Ci[i] + e4.w);
                    if (d < bestv[i]) { bestv[i] = d; besti[i] = vb + 3; }
                }
            }
        }
    }

    #pragma unroll
    for (int i = 0; i < 8; i++) {
        float v = bestv[i];
        int   idx = besti[i];
        #pragma unroll
        for (int off = 8; off > 0; off >>= 1) {
            float ov = __shfl_xor_sync(0xffffffffu, v, off);
            int   oi = __shfl_xor_sync(0xffffffffu, idx, off);
            if (ov < v || (ov == v && oi < idx)) { v = ov; idx = oi; }
        }
        if (tx == 0) {
            int n = m0 + row0 + i;
            g_pv[chunk][n] = v;
            g_pi[chunk][n] = idx;
        }
    }
    #undef LOAD_TILE
    #undef STS_A_B01
    #undef STS_B23
    #undef COMPUTE_KK
}

// ============================================================
// Kernel 3: merge chunk argmins + write tokens and z_q
// (z_q = bias + sum of 4 pmat partials at tok, ascending kb)
// ============================================================
__global__ __launch_bounds__(256) void merge_gather(
    const float* __restrict__ post_b,
    float* __restrict__ out_tok, float* __restrict__ out_zq)
{
    int n    = blockIdx.x * 8 + (threadIdx.x >> 5);
    int lane = threadIdx.x & 31;

    int tok = 0;
    if (lane == 0) {
        float bv = g_pv[0][n];
        int   bi = g_pi[0][n];
        #pragma unroll
        for (int c = 1; c < NCHUNK; c++) {
            float v = g_pv[c][n];
            int   i = g_pi[c][n];
            if (v < bv) { bv = v; bi = i; }
        }
        tok = bi;
        out_tok[n] = (float)bi;
    }
    tok = __shfl_sync(0xffffffffu, tok, 0);
    if (lane < 16) {
        float4 a = *(const float4*)&post_b[lane * 4];
        #pragma unroll
        for (int kb = 0; kb < PKB; kb++) {
            float4 p = *(const float4*)&g_Pp[kb][(size_t)tok * 64 + lane * 4];
            a.x += p.x; a.y += p.y; a.z += p.z; a.w += p.w;
        }
        *(float4*)&out_zq[(size_t)n * 64 + lane * 4] = a;
    }
}

// ============================================================
extern "C" void kernel_launch(void* const* d_in, const int* in_sizes, int n_in,
                              void* d_out, int out_size)
{
    const float* z      = (const float*)d_in[0];
    const float* emb_W  = (const float*)d_in[1];
    const float* pre_W  = (const float*)d_in[2];
    const float* pre_b  = (const float*)d_in[3];
    const float* post_W = (const float*)d_in[4];
    const float* post_b = (const float*)d_in[5];

    float* out = (float*)d_out;
    float* out_tok = out;
    float* out_zq  = out + N_TOK;

    const int PMAT_SMEM = 2 * 32 * 68 * 4;   // 17408 bytes dynamic

    dim3 pgrid(NBX_PRE + NBX_E2, E_DIM / 128);
    pre_gemm  <<<pgrid, 256>>>(z, pre_W, pre_b, emb_W);

    dim3 dgrid(NBX_DIST + NBX_PMAT, NCHUNK);
    dist_kernel<<<dgrid, 256, PMAT_SMEM>>>(emb_W, post_W);

    merge_gather<<<N_TOK / 8, 256>>>(post_b, out_tok, out_zq);
}

// round 17
// speedup vs baseline: 1.0177x; 1.0177x over previous
#include <cuda_runtime.h>
#include <cstdint>

#define N_TOK   65536
#define K_IN    64
#define E_DIM   512
#define V_SIZE  2048
#define NCHUNK  2
#define VCHUNK  (V_SIZE / NCHUNK)
#define PKB     4                    // pmat split-K factor
#define NBX_DIST (N_TOK / 128)       // 512 dist blocks in x
#define NBX_PMAT (V_SIZE / 64 * PKB / NCHUNK)   // 64 extra x-blocks
#define PM      128                  // pre rows per block
#define NBX_PRE (N_TOK / PM)         // 512 pre blocks in x
#define NBX_E2  (V_SIZE / 2)         // 1024 extra x-blocks (2 codes each)

#define A_PAD   132                  // row stride for transposed As
                                     // (132*4 B ≡ 0 mod 16 -> aligned LDS.128)

typedef unsigned long long ull;

// ---- scratch ----
__device__ float g_zp[(size_t)N_TOK * E_DIM];
__device__ float g_Cp[4][N_TOK];                 // per-j-block |zp|^2 partials
__device__ float g_e2[V_SIZE];
__device__ float g_Pp[PKB][(size_t)V_SIZE * 64]; // pmat k-partials
__device__ float g_pv[NCHUNK][N_TOK];
__device__ int   g_pi[NCHUNK][N_TOK];

// ---- packed fp32x2 helpers (exact IEEE fp32 per lane) ----
__device__ __forceinline__ ull fma2(ull a, ull b, ull c) {
    ull d; asm("fma.rn.f32x2 %0, %1, %2, %3;" : "=l"(d) : "l"(a), "l"(b), "l"(c)); return d;
}
__device__ __forceinline__ ull dup2(float x) {
    ull d; asm("mov.b64 %0, {%1, %1};" : "=l"(d) : "f"(x)); return d;
}
__device__ __forceinline__ ull pack2(float x, float y) {
    ull d; asm("mov.b64 %0, {%1, %2};" : "=l"(d) : "f"(x), "f"(y)); return d;
}
__device__ __forceinline__ float2 unpack2(ull v) {
    float2 r; asm("mov.b64 {%0, %1}, %2;" : "=f"(r.x), "=f"(r.y) : "l"(v)); return r;
}

// ============================================================
// e2 body: bitwise-exact replica of the validated e2_kernel
// ============================================================
__device__ __forceinline__ void e2_body(const float* __restrict__ emb, int v)
{
    __shared__ float ws2[2][4];
    int ltid = threadIdx.x & 127;
    int half = threadIdx.x >> 7;

    const float* row = emb + (size_t)v * E_DIM;
    float s = 0.f;
    for (int k = ltid; k < E_DIM; k += 128) {
        float x = row[k];
        s = fmaf(x, x, s);
    }
    for (int off = 16; off > 0; off >>= 1)
        s += __shfl_down_sync(0xffffffffu, s, off);
    int lane = ltid & 31, warp = ltid >> 5;
    if (lane == 0) ws2[half][warp] = s;
    __syncthreads();
    if (ltid == 0)
        g_e2[v] = ws2[half][0] + ws2[half][1] + ws2[half][2] + ws2[half][3];
}

// ============================================================
// Kernel 1: pre GEMM v2 — 128x128 block, 8x8 per thread,
// As stored k-major (transposed, A_PAD=132 -> aligned float4).
// Per-output chain unchanged (bias init, k 0..63 ascending)
// -> bitwise zp; C partial chain identical -> bitwise g_Cp.
// e2 blocks appended in x (y==0 only).
// ============================================================
#define PRE_SMEM ((64 * A_PAD + 64 * 128) * 4)   // 66560 bytes

__global__ __launch_bounds__(256) void pre_gemm(
    const float* __restrict__ z, const float* __restrict__ W,
    const float* __restrict__ b, const float* __restrict__ emb)
{
    if (blockIdx.x >= NBX_PRE) {
        if (blockIdx.y != 0) return;
        int ex = blockIdx.x - NBX_PRE;
        e2_body(emb, ex * 2 + (threadIdx.x >> 7));
        return;
    }

    extern __shared__ float psm[];
    float* As = psm;                 // [64][A_PAD]  (k-major)
    float* Ws = psm + 64 * A_PAD;    // [64][128]

    int m0 = blockIdx.x * PM;
    int jb = blockIdx.y;
    int j0 = jb * 128;
    int tid = threadIdx.x;
    int tx = tid & 15;
    int ty = tid >> 4;

    // load z tile 128x64 -> As transposed (coalesced LDG)
    #pragma unroll
    for (int l = 0; l < 8; l++) {
        int idx = tid + 256 * l;
        int row = idx >> 4, q = idx & 15;
        float4 v = *(const float4*)(z + (size_t)(m0 + row) * K_IN + q * 4);
        As[(q * 4 + 0) * A_PAD + row] = v.x;
        As[(q * 4 + 1) * A_PAD + row] = v.y;
        As[(q * 4 + 2) * A_PAD + row] = v.z;
        As[(q * 4 + 3) * A_PAD + row] = v.w;
    }
    // load W tile 64x128 (already k-major)
    #pragma unroll
    for (int l = 0; l < 8; l++) {
        int idx = tid + 256 * l;
        int k = idx >> 5, c4 = idx & 31;
        *(float4*)&Ws[k * 128 + c4 * 4] =
            *(const float4*)(W + (size_t)k * E_DIM + j0 + c4 * 4);
    }
    __syncthreads();

    float4 bl0 = *(const float4*)&b[j0 + tx * 8];
    float4 bl1 = *(const float4*)&b[j0 + tx * 8 + 4];
    ull acc[8][4];
    #pragma unroll
    for (int i = 0; i < 8; i++) {
        acc[i][0] = pack2(bl0.x, bl0.y);
        acc[i][1] = pack2(bl0.z, bl0.w);
        acc[i][2] = pack2(bl1.x, bl1.y);
        acc[i][3] = pack2(bl1.z, bl1.w);
    }

    #pragma unroll 8
    for (int kk = 0; kk < K_IN; kk++) {
        const float* ar = As + kk * A_PAD + ty * 8;
        float4 a01 = *(const float4*)ar;
        float4 a23 = *(const float4*)(ar + 4);
        const float* wr = Ws + kk * 128 + tx * 8;
        float4 w0 = *(const float4*)wr;
        float4 w1 = *(const float4*)(wr + 4);
        ull b0 = pack2(w0.x, w0.y), b1 = pack2(w0.z, w0.w);
        ull b2 = pack2(w1.x, w1.y), b3 = pack2(w1.z, w1.w);
        ull ad[8];
        ad[0] = dup2(a01.x); ad[1] = dup2(a01.y);
        ad[2] = dup2(a01.z); ad[3] = dup2(a01.w);
        ad[4] = dup2(a23.x); ad[5] = dup2(a23.y);
        ad[6] = dup2(a23.z); ad[7] = dup2(a23.w);
        #pragma unroll
        for (int i = 0; i < 8; i++) {
            acc[i][0] = fma2(ad[i], b0, acc[i][0]);
            acc[i][1] = fma2(ad[i], b1, acc[i][1]);
            acc[i][2] = fma2(ad[i], b2, acc[i][2]);
            acc[i][3] = fma2(ad[i], b3, acc[i][3]);
        }
    }

    #pragma unroll
    for (int i = 0; i < 8; i++) {
        int n = m0 + ty * 8 + i;
        float2 p0 = unpack2(acc[i][0]), p1 = unpack2(acc[i][1]);
        float2 p2 = unpack2(acc[i][2]), p3 = unpack2(acc[i][3]);
        float4 r0; r0.x = p0.x; r0.y = p0.y; r0.z = p1.x; r0.w = p1.y;
        float4 r1; r1.x = p2.x; r1.y = p2.y; r1.z = p3.x; r1.w = p3.y;
        float* dst = g_zp + (size_t)n * E_DIM + j0 + tx * 8;
        *(float4*)dst = r0;
        *(float4*)(dst + 4) = r1;

        // C partial: identical 8-element fmaf chain + 16-lane tree
        float s = r0.x * r0.x;
        s = fmaf(r0.y, r0.y, s);
        s = fmaf(r0.z, r0.z, s);
        s = fmaf(r0.w, r0.w, s);
        s = fmaf(r1.x, r1.x, s);
        s = fmaf(r1.y, r1.y, s);
        s = fmaf(r1.z, r1.z, s);
        s = fmaf(r1.w, r1.w, s);
        #pragma unroll
        for (int off = 8; off > 0; off >>= 1)
            s += __shfl_xor_sync(0xffffffffu, s, off);
        if (tx == 0) g_Cp[jb][n] = s;
    }
}

// ============================================================
// pmat body (split-K partials, PKB=4), run by extra dist blocks
// ============================================================
__device__ __forceinline__ void pmat_body(
    const float* __restrict__ emb, const float* __restrict__ W, int ex)
{
    extern __shared__ float dsm[];
    float (*As2)[64 + 4] = (float(*)[64 + 4])dsm;              // [32][68]
    float (*Bs2)[64 + 4] = (float(*)[64 + 4])(dsm + 32 * 68);  // [32][68]

    int m0  = (ex & 31) * 64;
    int kb  = ex >> 5;                 // 0..3
    int tid = threadIdx.x;
    int tx  = tid & 15;
    int ty  = tid >> 4;

    float acc[4][4];
    #pragma unroll
    for (int i = 0; i < 4; i++)
        #pragma unroll
        for (int jj = 0; jj < 4; jj++) acc[i][jj] = 0.f;

    for (int k0 = kb * 128; k0 < kb * 128 + 128; k0 += 32) {
        #pragma unroll
        for (int i = 0; i < 8; i++) {
            int idx = tid + 256 * i;
            int m = idx >> 5, kk = idx & 31;
            As2[kk][m] = emb[(size_t)(m0 + m) * E_DIM + k0 + kk];
        }
        #pragma unroll
        for (int i = 0; i < 8; i++) {
            int idx = tid + 256 * i;
            int kk = idx >> 6, jj = idx & 63;
            Bs2[kk][jj] = W[(size_t)(k0 + kk) * 64 + jj];
        }
        __syncthreads();
        #pragma unroll
        for (int kk = 0; kk < 32; kk++) {
            float a[4], bb[4];
            *(float4*)a  = *(const float4*)&As2[kk][ty * 4];
            *(float4*)bb = *(const float4*)&Bs2[kk][tx * 4];
            #pragma unroll
            for (int i = 0; i < 4; i++)
                #pragma unroll
                for (int jj = 0; jj < 4; jj++)
                    acc[i][jj] = fmaf(a[i], bb[jj], acc[i][jj]);
        }
        __syncthreads();
    }

    #pragma unroll
    for (int i = 0; i < 4; i++) {
        int n = m0 + ty * 4 + i;
        float4 r;
        r.x = acc[i][0];
        r.y = acc[i][1];
        r.z = acc[i][2];
        r.w = acc[i][3];
        *(float4*)&g_Pp[kb][(size_t)n * 64 + tx * 4] = r;
    }
}

// ============================================================
// Kernel 2: fused distance GEMM + argmin (R11 verbatim) +
// pmat blocks appended in x.  Bitwise tokens.
// ============================================================
#define DBM 128
#define DBV 256
#define DBK 16
#define NKT (E_DIM / DBK)          // 32
#define NVT (VCHUNK / DBV)         // 4
#define NT  (NKT * NVT)            // 128

__global__ __launch_bounds__(256, 1) void dist_kernel(
    const float* __restrict__ emb, const float* __restrict__ postW)
{
    if (blockIdx.x >= NBX_DIST) {
        int ex = (blockIdx.x - NBX_DIST) * NCHUNK + blockIdx.y;
        pmat_body(emb, postW, ex);
        return;
    }

    __shared__ float As[2][DBK][DBM];
    __shared__ float Bs[2][DBK][DBV];
    __shared__ float sE2[VCHUNK];

    int m0 = blockIdx.x * DBM;
    int chunk = blockIdx.y;
    int vc = chunk * VCHUNK;

    int tid = threadIdx.x;
    int tx  = tid & 15;
    int ty  = tid >> 4;
    int row0 = ty * 8;

    int mA  = tid >> 2;
    int kq4 = (tid & 3) * 4;
    int sw  = kq4 << 1;
    int mAx = mA ^ sw;

    const float* aBase = g_zp + (size_t)(m0 + mA) * E_DIM + kq4;
    const float* bBase = emb  + (size_t)(vc + mA) * E_DIM + kq4;

    float Ci[8];
    #pragma unroll
    for (int i = 0; i < 8; i++) {
        int n = m0 + row0 + i;
        Ci[i] = ((g_Cp[0][n] + g_Cp[1][n]) + g_Cp[2][n]) + g_Cp[3][n];
    }

    float bestv[8];
    int   besti[8];
    #pragma unroll
    for (int i = 0; i < 8; i++) { bestv[i] = 3.4e38f; besti[i] = 0; }

    ull acc[8][8];
    float4 pA0, pA1, pB0, pB1, pB2, pB3;

    #define LOAD_TILE(tt) do {                                              \
        int _k = ((tt) & (NKT - 1)) * DBK;                                  \
        int _v = ((tt) >> 5) * DBV;                                         \
        pA0 = *(const float4*)(aBase + _k);                                 \
        pA1 = *(const float4*)(aBase + (size_t)64 * E_DIM + _k);            \
        const float* _bb = bBase + (size_t)_v * E_DIM + _k;                 \
        pB0 = *(const float4*)(_bb);                                        \
        pB1 = *(const float4*)(_bb + (size_t)64  * E_DIM);                  \
        pB2 = *(const float4*)(_bb + (size_t)128 * E_DIM);                  \
        pB3 = *(const float4*)(_bb + (size_t)192 * E_DIM);                  \
    } while (0)

    #define STS_A_B01(bf) do {                                              \
        float* _a = &As[bf][kq4][0];                                        \
        _a[0*DBM + mAx]      = pA0.x; _a[1*DBM + mAx]      = pA0.y;         \
        _a[2*DBM + mAx]      = pA0.z; _a[3*DBM + mAx]      = pA0.w;         \
        _a[0*DBM + mAx + 64] = pA1.x; _a[1*DBM + mAx + 64] = pA1.y;         \
        _a[2*DBM + mAx + 64] = pA1.z; _a[3*DBM + mAx + 64] = pA1.w;         \
        float* _b = &Bs[bf][kq4][0];                                        \
        _b[0*DBV + mAx]       = pB0.x; _b[1*DBV + mAx]       = pB0.y;       \
        _b[2*DBV + mAx]       = pB0.z; _b[3*DBV + mAx]       = pB0.w;       \
        _b[0*DBV + mAx + 64]  = pB1.x; _b[1*DBV + mAx + 64]  = pB1.y;       \
        _b[2*DBV + mAx + 64]  = pB1.z; _b[3*DBV + mAx + 64]  = pB1.w;       \
    } while (0)

    #define STS_B23(bf) do {                                                \
        float* _b = &Bs[bf][kq4][0];                                        \
        _b[0*DBV + mAx + 128] = pB2.x; _b[1*DBV + mAx + 128] = pB2.y;       \
        _b[2*DBV + mAx + 128] = pB2.z; _b[3*DBV + mAx + 128] = pB2.w;       \
        _b[0*DBV + mAx + 192] = pB3.x; _b[1*DBV + mAx + 192] = pB3.y;       \
        _b[2*DBV + mAx + 192] = pB3.z; _b[3*DBV + mAx + 192] = pB3.w;       \
    } while (0)

    #define COMPUTE_KK(bf, kk) do {                                         \
        const int s = ((kk) & 12) << 1;                                     \
        float4 a01 = *(const float4*)&As[bf][kk][(row0 ^ s)];               \
        float4 a23 = *(const float4*)&As[bf][kk][(row0 ^ s) + 4];           \
        ull ad[8];                                                          \
        ad[0] = dup2(a01.x); ad[1] = dup2(a01.y);                           \
        ad[2] = dup2(a01.z); ad[3] = dup2(a01.w);                           \
        ad[4] = dup2(a23.x); ad[5] = dup2(a23.y);                           \
        ad[6] = dup2(a23.z); ad[7] = dup2(a23.w);                           \
        _Pragma("unroll")                                                   \
        for (int g = 0; g < 4; g++) {                                       \
            float4 b = *(const float4*)&Bs[bf][kk][(((g * 16 + tx) * 4) ^ s)]; \
            ull b0 = pack2(b.x, b.y);                                       \
            ull b1 = pack2(b.z, b.w);                                       \
            _Pragma("unroll")                                               \
            for (int i = 0; i < 8; i++) {                                   \
                acc[i][g * 2 + 0] = fma2(ad[i], b0, acc[i][g * 2 + 0]);     \
                acc[i][g * 2 + 1] = fma2(ad[i], b1, acc[i][g * 2 + 1]);     \
            }                                                               \
        }                                                                   \
    } while (0)

    LOAD_TILE(0);
    STS_A_B01(0);
    STS_B23(0);
    {
        float4 v = *(const float4*)&g_e2[vc + tid * 4];
        *(float4*)&sE2[tid * 4] = v;
    }
    LOAD_TILE(1);
    __syncthreads();

    for (int t = 0; t < NT; t++) {
        int buf = t & 1;
        bool more = (t + 1 < NT);

        if ((t & (NKT - 1)) == 0) {
            #pragma unroll
            for (int i = 0; i < 8; i++)
                #pragma unroll
                for (int j = 0; j < 8; j++) acc[i][j] = 0ull;
        }

        #pragma unroll
        for (int kk = 0; kk < 4; kk++) COMPUTE_KK(buf, kk);

        if (more) STS_A_B01(buf ^ 1);

        #pragma unroll
        for (int kk = 4; kk < 8; kk++) COMPUTE_KK(buf, kk);

        if (more) STS_B23(buf ^ 1);

        #pragma unroll
        for (int kk = 8; kk < 12; kk++) COMPUTE_KK(buf, kk);

        if (more) {
            int tt = (t + 2 < NT) ? t + 2 : NT - 1;
            LOAD_TILE(tt);
        }

        #pragma unroll
        for (int kk = 12; kk < DBK; kk++) COMPUTE_KK(buf, kk);

        __syncthreads();

        if ((t & (NKT - 1)) == NKT - 1) {
            int lv0 = (t >> 5) * DBV;
            #pragma unroll
            for (int g = 0; g < 4; g++) {
                int lvb = lv0 + (g * 16 + tx) * 4;
                float4 e4 = *(const float4*)&sE2[lvb];
                int vb = vc + lvb;
                #pragma unroll
                for (int i = 0; i < 8; i++) {
                    float2 p0 = unpack2(acc[i][g * 2 + 0]);
                    float2 p1 = unpack2(acc[i][g * 2 + 1]);
                    float d;
                    d = fmaf(-2.0f, p0.x, Ci[i] + e4.x);
                    if (d < bestv[i]) { bestv[i] = d; besti[i] = vb + 0; }
                    d = fmaf(-2.0f, p0.y, Ci[i] + e4.y);
                    if (d < bestv[i]) { bestv[i] = d; besti[i] = vb + 1; }
                    d = fmaf(-2.0f, p1.x, Ci[i] + e4.z);
                    if (d < bestv[i]) { bestv[i] = d; besti[i] = vb + 2; }
                    d = fmaf(-2.0f, p1.y, Ci[i] + e4.w);
                    if (d < bestv[i]) { bestv[i] = d; besti[i] = vb + 3; }
                }
            }
        }
    }

    #pragma unroll
    for (int i = 0; i < 8; i++) {
        float v = bestv[i];
        int   idx = besti[i];
        #pragma unroll
        for (int off = 8; off > 0; off >>= 1) {
            float ov = __shfl_xor_sync(0xffffffffu, v, off);
            int   oi = __shfl_xor_sync(0xffffffffu, idx, off);
            if (ov < v || (ov == v && oi < idx)) { v = ov; idx = oi; }
        }
        if (tx == 0) {
            int n = m0 + row0 + i;
            g_pv[chunk][n] = v;
            g_pi[chunk][n] = idx;
        }
    }
    #undef LOAD_TILE
    #undef STS_A_B01
    #undef STS_B23
    #undef COMPUTE_KK
}

// ============================================================
// Kernel 3: merge chunk argmins + write tokens and z_q
// ============================================================
__global__ __launch_bounds__(256) void merge_gather(
    const float* __restrict__ post_b,
    float* __restrict__ out_tok, float* __restrict__ out_zq)
{
    int n    = blockIdx.x * 8 + (threadIdx.x >> 5);
    int lane = threadIdx.x & 31;

    int tok = 0;
    if (lane == 0) {
        float bv = g_pv[0][n];
        int   bi = g_pi[0][n];
        #pragma unroll
        for (int c = 1; c < NCHUNK; c++) {
            float v = g_pv[c][n];
            int   i = g_pi[c][n];
            if (v < bv) { bv = v; bi = i; }
        }
        tok = bi;
        out_tok[n] = (float)bi;
    }
    tok = __shfl_sync(0xffffffffu, tok, 0);
    if (lane < 16) {
        float4 a = *(const float4*)&post_b[lane * 4];
        #pragma unroll
        for (int kb = 0; kb < PKB; kb++) {
            float4 p = *(const float4*)&g_Pp[kb][(size_t)tok * 64 + lane * 4];
            a.x += p.x; a.y += p.y; a.z += p.z; a.w += p.w;
        }
        *(float4*)&out_zq[(size_t)n * 64 + lane * 4] = a;
    }
}

// ============================================================
extern "C" void kernel_launch(void* const* d_in, const int* in_sizes, int n_in,
                              void* d_out, int out_size)
{
    const float* z      = (const float*)d_in[0];
    const float* emb_W  = (const float*)d_in[1];
    const float* pre_W  = (const float*)d_in[2];
    const float* pre_b  = (const float*)d_in[3];
    const float* post_W = (const float*)d_in[4];
    const float* post_b = (const float*)d_in[5];

    float* out = (float*)d_out;
    float* out_tok = out;
    float* out_zq  = out + N_TOK;

    const int PMAT_SMEM = 2 * 32 * 68 * 4;   // 17408 bytes dynamic

    cudaFuncSetAttribute(pre_gemm,
                         cudaFuncAttributeMaxDynamicSharedMemorySize, PRE_SMEM);

    dim3 pgrid(NBX_PRE + NBX_E2, E_DIM / 128);
    pre_gemm  <<<pgrid, 256, PRE_SMEM>>>(z, pre_W, pre_b, emb_W);

    dim3 dgrid(NBX_DIST + NBX_PMAT, NCHUNK);
    dist_kernel<<<dgrid, 256, PMAT_SMEM>>>(emb_W, post_W);

    merge_gather<<<N_TOK / 8, 256>>>(post_b, out_tok, out_zq);
}